// round 8
// baseline (speedup 1.0000x reference)
#include <cuda_runtime.h>

#define H 512
#define W 512
#define NIMG 48
#define ROWS 8
#define CPT 8
#define STRIPS_X (W / CPT)                      // 64
#define STRIPS_Y (H / ROWS)                     // 64
#define THREADS_PER_IMG (STRIPS_X * STRIPS_Y)   // 4096
#define BLOCK 128

__device__ __forceinline__ float med3f(float a, float b, float c) {
    return fmaxf(fminf(a, b), fminf(fmaxf(a, b), c));
}

// Load cols [c0-1, c0+8] of one row into d[0..9] using 4 vector loads.
//  dl/dr are loop-invariant float offsets (clamped in-bounds at image edges);
//  eL/eR select in-register reflection for the image-border strips.
__device__ __forceinline__ void load10(const float* __restrict__ pv,
                                       int dl, int dr, bool eL, bool eR,
                                       float* __restrict__ d) {
    const float4 vm = *reinterpret_cast<const float4*>(pv + dl);  // cols c0-4..c0-1
    const float4 v0 = *reinterpret_cast<const float4*>(pv);       // cols c0..c0+3
    const float4 v1 = *reinterpret_cast<const float4*>(pv + 4);   // cols c0+4..c0+7
    const float4 vp = *reinterpret_cast<const float4*>(pv + dr);  // cols c0+8..c0+11
    d[1] = v0.x; d[2] = v0.y; d[3] = v0.z; d[4] = v0.w;
    d[5] = v1.x; d[6] = v1.y; d[7] = v1.z; d[8] = v1.w;
    d[0] = eL ? v0.y : vm.w;   // reflect col -1 -> 1, else col c0-1
    d[9] = eR ? v1.z : vp.x;   // reflect col W -> W-2, else col c0+8
}

__global__ __launch_bounds__(BLOCK)
void MedianFilter_22737556865485_kernel(const float* __restrict__ in,
                                        float* __restrict__ out) {
    const int tid = blockIdx.x * BLOCK + threadIdx.x;
    const int img = tid / THREADS_PER_IMG;
    const int s   = tid % THREADS_PER_IMG;
    const int sx  = s % STRIPS_X;               // warp covers 32 consecutive strips
    const int sy  = s / STRIPS_X;
    const int c0  = sx * CPT;
    const int r0  = sy * ROWS;

    // Loop-invariant edge descriptors.
    const bool eL = (c0 == 0);
    const bool eR = (c0 + CPT == W);
    const int  dl = eL ? 0 : -4;                // clamped: edge strip re-reads own cols
    const int  dr = eR ? 4 : 8;
    const bool lastStrip = (r0 == H - ROWS);    // only strip whose prefetch hits row H

    const float* base  = in  + (size_t)img * (H * W);
    float*       obase = out + (size_t)img * (H * W);

    const float* prow = base + (size_t)r0 * W + c0;
    float*       po   = obase + (size_t)r0 * W + c0;

    float b0[10], b1[10], b2[10], pm[10], pM[10];

    // Prologue: rows r0-1 (reflect -1 -> 1) and r0 -> pair cache; row r0+1 loaded.
    {
        float t[10];
        const float* pmrow = base + (size_t)((r0 == 0) ? 1 : (r0 - 1)) * W + c0;
        load10(pmrow, dl, dr, eL, eR, t);
        load10(prow,  dl, dr, eL, eR, b0);
#pragma unroll
        for (int c = 0; c < 10; ++c) {
            pm[c] = fminf(t[c], b0[c]);
            pM[c] = fmaxf(t[c], b0[c]);
        }
        load10(prow + W, dl, dr, eL, eR, b1);
    }

    const float* pv = prow + 2 * W;             // next row to load = r0+2
    // Pointer for the single reflected prefetch (row H -> H-2), hoisted.
    // Step i loads row r0+i+2; only i==ROWS-2 on the last strip reflects.

    float* bufs[3] = {b0, b1, b2};              // resolved at compile time (full unroll)

#pragma unroll
    for (int i = 0; i < ROWS; ++i) {
        float* cur = bufs[i % 3];               // row r0+i   (expanded, resident)
        float* nxt = bufs[(i + 1) % 3];         // row r0+i+1 (resident)
        float* pf  = bufs[(i + 2) % 3];         // target for row r0+i+2

        if (i < ROWS - 1) {                     // compile-time
            const float* p = (i == ROWS - 2 && lastStrip) ? (pv - 2 * W) : pv;
            load10(p, dl, dr, eL, eR, pf);
            pv += W;
        }

        float lo[10], hi[10], mid[10];
#pragma unroll
        for (int c = 0; c < 10; ++c) {
            const float n = nxt[c];
            lo[c]  = fminf(pm[c], n);                  // min of column triple
            hi[c]  = fmaxf(pM[c], n);                  // max of column triple
            mid[c] = fmaxf(fminf(pM[c], n), pm[c]);    // mid of column triple
            pm[c]  = fminf(cur[c], n);                 // pair cache -> (r, r+1)
            pM[c]  = fmaxf(cur[c], n);
        }

        float o[CPT];
#pragma unroll
        for (int j = 0; j < CPT; ++j) {
            const float A = fmaxf(fmaxf(lo[j], lo[j + 1]), lo[j + 2]);  // max of mins
            const float C = fminf(fminf(hi[j], hi[j + 1]), hi[j + 2]);  // min of maxes
            const float B = med3f(mid[j], mid[j + 1], mid[j + 2]);      // med of mids
            o[j] = med3f(A, B, C);                                      // exact median9
        }

        *reinterpret_cast<float4*>(po)     = make_float4(o[0], o[1], o[2], o[3]);
        *reinterpret_cast<float4*>(po + 4) = make_float4(o[4], o[5], o[6], o[7]);
        po += W;
    }
}

extern "C" void kernel_launch(void* const* d_in, const int* in_sizes, int n_in,
                              void* d_out, int out_size) {
    const float* in  = (const float*)d_in[0];
    float*       out = (float*)d_out;
    const int total_threads = NIMG * THREADS_PER_IMG;   // 196608
    MedianFilter_22737556865485_kernel<<<total_threads / BLOCK, BLOCK>>>(in, out);
}